// round 13
// baseline (speedup 1.0000x reference)
#include <cuda_runtime.h>
#include <math.h>

#define NA 8192
#define SD 64
#define HD 128
#define CD 32
#define AD 8
#define NB 128
#define NT 512
#define ROWS 64

// -------- device scratch (zero-initialized; kernel self-resets counters) ----
__device__ float g_W2c[HD * CD];        // K-major: [k][c]
__device__ float g_bc2[CD];
__device__ float g_msgpart[NB * CD];    // per-CTA msum partials
__device__ float g_hpart[NB * HD];      // per-CTA hsum partials
__device__ unsigned g_barW, g_barA, g_barB, g_done;

typedef unsigned long long ull;

__device__ __forceinline__ ull pack2(float lo, float hi) {
    ull r;
    asm("mov.b64 %0, {%1, %2};" : "=l"(r) : "f"(lo), "f"(hi));
    return r;
}
__device__ __forceinline__ void unpack2(ull v, float& lo, float& hi) {
    asm("mov.b64 {%0, %1}, %2;" : "=f"(lo), "=f"(hi) : "l"(v));
}
__device__ __forceinline__ ull fma2(ull a, ull b, ull c) {
    ull d;
    asm("fma.rn.f32x2 %0, %1, %2, %3;" : "=l"(d) : "l"(a), "l"(b), "l"(c));
    return d;
}

// ---- split grid barrier: release-arrive / acquire-wait ----
__device__ __forceinline__ void bar_arrive(unsigned* ctr) {
    __syncthreads();
    if (threadIdx.x == 0)
        asm volatile("red.release.gpu.global.add.u32 [%0], 1;"
                     :: "l"(ctr) : "memory");
}
__device__ __forceinline__ void bar_wait(unsigned* ctr) {
    if (threadIdx.x == 0) {
        unsigned v;
        do {
            asm volatile("ld.acquire.gpu.global.u32 %0, [%1];"
                         : "=r"(v) : "l"(ctr) : "memory");
        } while (v < (unsigned)NB);
    }
    __syncthreads();
}

__global__ void __launch_bounds__(NT, 1) kfused(
    const float* __restrict__ states, const float* __restrict__ noise,
    const float* __restrict__ W1, const float* __restrict__ b1,
    const float* __restrict__ W2, const float* __restrict__ b2,
    const float* __restrict__ Wc, const float* __restrict__ bc,
    const float* __restrict__ Wg, const float* __restrict__ bg,
    const float* __restrict__ Wp, const float* __restrict__ bp,
    const float* __restrict__ Wv, const float* __restrict__ bv,
    const float* __restrict__ Wr, const float* __restrict__ br,
    float* __restrict__ outH, float* __restrict__ outA,
    float* __restrict__ outV, float* __restrict__ outR) {

    extern __shared__ float sm[];
    float* s_s   = sm;              // 4096: states row-interleaved; later W1comm
    float* s_wh  = s_s + 4096;      // 8192: W1[0:64][128]; later h[64][128]
    float* s_w2c = s_wh + 8192;     // 4096: W2c K-major [k][32]
    float* s_ms  = s_w2c + 4096;    // 32
    float* s_bc2 = s_ms + 32;       // 32
    float* s_mh  = s_bc2 + 32;      // 128
    float* s_h2  = s_mh + 128;      // 128
    float* s_g   = s_h2 + 128;      // 128
    float* s_prt = s_g + 128;       // 8*128 = 1024
    float* s_hw  = s_prt + 1024;    // 1536  head weights [k][12]

    int t = threadIdx.x;
    int bid = blockIdx.x;
    int r0 = bid * ROWS;
    int w = t >> 5, l = t & 31;

    // ---- distributed W2c fold: 2 dots per warp ----
    {
#pragma unroll
        for (int e = 0; e < 2; e++) {
            int idx = bid * 32 + w * 2 + e;        // 0..4095
            int c = idx & 31, k = idx >> 5;
            float4 w2v = *(const float4*)&W2[k * HD + l * 4];
            float d = w2v.x * Wc[(l * 4 + 0) * CD + c] +
                      w2v.y * Wc[(l * 4 + 1) * CD + c] +
                      w2v.z * Wc[(l * 4 + 2) * CD + c] +
                      w2v.w * Wc[(l * 4 + 3) * CD + c];
#pragma unroll
            for (int o = 16; o; o >>= 1) d += __shfl_xor_sync(0xffffffffu, d, o);
            if (l == 0) g_W2c[k * CD + c] = d;
        }
        if (bid == 1) {
#pragma unroll
            for (int e = 0; e < 2; e++) {
                int c = w * 2 + e;
                float4 b2v = *(const float4*)&b2[l * 4];
                float d = b2v.x * Wc[(l * 4 + 0) * CD + c] +
                          b2v.y * Wc[(l * 4 + 1) * CD + c] +
                          b2v.z * Wc[(l * 4 + 2) * CD + c] +
                          b2v.w * Wc[(l * 4 + 3) * CD + c];
#pragma unroll
                for (int o = 16; o; o >>= 1) d += __shfl_xor_sync(0xffffffffu, d, o);
                if (l == 0) g_bc2[c] = d + bc[c];
            }
        }
    }

    bar_arrive(&g_barW);    // W2c/bc2 published; wait deferred past phase 1

    // ---- stage: states (row-interleaved pairs), W1[0:64], head weights ----
    for (int i = t; i < ROWS * SD; i += NT) {
        int rp = i >> 7, rem = i & 127, k = rem >> 1, sub = rem & 1;
        s_s[i] = states[(size_t)(r0 + 2 * rp + sub) * SD + k];
    }
    ((float4*)s_wh)[t]        = ((const float4*)W1)[t];
    ((float4*)s_wh)[t +  512] = ((const float4*)W1)[t +  512];
    ((float4*)s_wh)[t + 1024] = ((const float4*)W1)[t + 1024];
    ((float4*)s_wh)[t + 1536] = ((const float4*)W1)[t + 1536];
    for (int i = t; i < HD * 12; i += NT) {
        int k = i / 12, j = i % 12;
        float v;
        if (j < 8)       v = Wp[k * AD + j];
        else if (j == 8) v = Wv[k];
        else             v = Wr[k * 3 + (j - 9)];
        s_hw[i] = v;
    }
    __syncthreads();

    // ---- phase 1: P = states @ W1[:64], packed row-pairs (FFMA2) ----
    int c0 = (t & 63) * 2;
    int rg = t >> 6;              // 0..7 -> rows rg*8 .. rg*8+7
    int rp0 = rg * 4;             // 4 row-pairs
    float2 b1v = *(const float2*)&b1[c0];
    ull acc[4][2];
#pragma unroll
    for (int r = 0; r < 4; r++) { acc[r][0] = 0ull; acc[r][1] = 0ull; }

#pragma unroll 4
    for (int k = 0; k < SD; k += 4) {
        float2 wv0 = *(const float2*)&s_wh[(k + 0) * HD + c0];
        float2 wv1 = *(const float2*)&s_wh[(k + 1) * HD + c0];
        float2 wv2 = *(const float2*)&s_wh[(k + 2) * HD + c0];
        float2 wv3 = *(const float2*)&s_wh[(k + 3) * HD + c0];
        ull w00 = pack2(wv0.x, wv0.x), w01 = pack2(wv0.y, wv0.y);
        ull w10 = pack2(wv1.x, wv1.x), w11 = pack2(wv1.y, wv1.y);
        ull w20 = pack2(wv2.x, wv2.x), w21 = pack2(wv2.y, wv2.y);
        ull w30 = pack2(wv3.x, wv3.x), w31 = pack2(wv3.y, wv3.y);
#pragma unroll
        for (int rp = 0; rp < 4; rp++) {
            ulonglong2 sa = *(const ulonglong2*)&s_s[(rp0 + rp) * 128 + k * 2];
            ulonglong2 sb = *(const ulonglong2*)&s_s[(rp0 + rp) * 128 + k * 2 + 4];
            acc[rp][0] = fma2(sa.x, w00, acc[rp][0]);
            acc[rp][1] = fma2(sa.x, w01, acc[rp][1]);
            acc[rp][0] = fma2(sa.y, w10, acc[rp][0]);
            acc[rp][1] = fma2(sa.y, w11, acc[rp][1]);
            acc[rp][0] = fma2(sb.x, w20, acc[rp][0]);
            acc[rp][1] = fma2(sb.x, w21, acc[rp][1]);
            acc[rp][0] = fma2(sb.y, w30, acc[rp][0]);
            acc[rp][1] = fma2(sb.y, w31, acc[rp][1]);
        }
    }
    __syncthreads();   // all W1/states reads complete

    // h = relu(P+b1) -> s_wh (reuse); stage W1 comm rows -> s_s (reuse)
#pragma unroll
    for (int rp = 0; rp < 4; rp++) {
        float x0, x1, y0, y1;
        unpack2(acc[rp][0], x0, x1);
        unpack2(acc[rp][1], y0, y1);
        int rowe = 2 * (rp0 + rp);
        *(float2*)&s_wh[rowe * HD + c0] =
            make_float2(fmaxf(x0 + b1v.x, 0.f), fmaxf(y0 + b1v.y, 0.f));
        *(float2*)&s_wh[(rowe + 1) * HD + c0] =
            make_float2(fmaxf(x1 + b1v.x, 0.f), fmaxf(y1 + b1v.y, 0.f));
    }
    ((float4*)s_s)[t]       = ((const float4*)(W1 + SD * HD))[t];
    ((float4*)s_s)[t + 512] = ((const float4*)(W1 + SD * HD))[t + 512];

    bar_wait(&g_barW);   // hidden behind phase 1

    // stage W2c (K-major) + bc2
    ((float4*)s_w2c)[t]       = ((const float4*)g_W2c)[t];
    ((float4*)s_w2c)[t + 512] = ((const float4*)g_W2c)[t + 512];
    if (t < CD) s_bc2[t] = g_bc2[t];
    __syncthreads();

    // ---- phase 2: msgs = l2norm(h @ W2c + bc2), all-warp-local reduction ----
    {
        int rrA = t >> 4;              // 0..31; also handles rrA+32
        int mcp = (t & 15) * 2;
        ull mA = *(const ull*)&s_bc2[mcp];
        ull mB = mA;
#pragma unroll 4
        for (int k = 0; k < HD; k += 4) {
            float4 hA = *(const float4*)&s_wh[rrA * HD + k];
            float4 hB = *(const float4*)&s_wh[(rrA + 32) * HD + k];
            ull wv0 = *(const ull*)&s_w2c[(k + 0) * CD + mcp];
            ull wv1 = *(const ull*)&s_w2c[(k + 1) * CD + mcp];
            ull wv2 = *(const ull*)&s_w2c[(k + 2) * CD + mcp];
            ull wv3 = *(const ull*)&s_w2c[(k + 3) * CD + mcp];
            mA = fma2(pack2(hA.x, hA.x), wv0, mA);
            mB = fma2(pack2(hB.x, hB.x), wv0, mB);
            mA = fma2(pack2(hA.y, hA.y), wv1, mA);
            mB = fma2(pack2(hB.y, hB.y), wv1, mB);
            mA = fma2(pack2(hA.z, hA.z), wv2, mA);
            mB = fma2(pack2(hB.z, hB.z), wv2, mB);
            mA = fma2(pack2(hA.w, hA.w), wv3, mA);
            mB = fma2(pack2(hB.w, hB.w), wv3, mB);
        }
        float a0, a1, b0v, b1x;
        unpack2(mA, a0, a1);
        unpack2(mB, b0v, b1x);
        float ssA = a0 * a0 + a1 * a1;
        float ssB = b0v * b0v + b1x * b1x;
#pragma unroll
        for (int o = 1; o <= 8; o <<= 1) {
            ssA += __shfl_xor_sync(0xffffffffu, ssA, o);
            ssB += __shfl_xor_sync(0xffffffffu, ssB, o);
        }
        float rnA = 1.f / fmaxf(sqrtf(ssA), 1e-12f);
        float rnB = 1.f / fmaxf(sqrtf(ssB), 1e-12f);
        float p0 = a0 * rnA + b0v * rnB;
        float p1 = a1 * rnA + b1x * rnB;
        p0 += __shfl_xor_sync(0xffffffffu, p0, 16);
        p1 += __shfl_xor_sync(0xffffffffu, p1, 16);
        if (l < 16) *(float2*)&s_prt[w * 32 + mcp] = make_float2(p0, p1);
    }
    __syncthreads();
    if (t < CD) {
        float p = 0.f;
#pragma unroll
        for (int w2 = 0; w2 < 16; w2++) p += s_prt[w2 * 32 + t];
        g_msgpart[bid * CD + t] = p;        // plain coalesced STG
    }

    bar_arrive(&g_barA);

    // ---- noise prefetch fills the barA gap ----
    int w5 = t >> 5, lane = t & 31;
    int rowb = r0 + w5 * 4;
    const float* nb = noise + (size_t)rowb * HD;
    float nz[4][4];
#pragma unroll
    for (int i = 0; i < 4; i++) {
        nz[i][0] = nb[i * HD + lane +  0];
        nz[i][1] = nb[i * HD + lane + 32];
        nz[i][2] = nb[i * HD + lane + 64];
        nz[i][3] = nb[i * HD + lane + 96];
    }

    bar_wait(&g_barA);

    // ---- parallel msum reduction ----
    {
        int c = t & 31, seg = t >> 5;       // 16 segs x 8 CTAs
        float p = 0.f;
#pragma unroll
        for (int i = 0; i < 8; i++) p += g_msgpart[(seg * 8 + i) * CD + c];
        s_prt[seg * 32 + c] = p;
    }
    __syncthreads();
    if (t < CD) {
        float p = 0.f;
#pragma unroll
        for (int s2 = 0; s2 < 16; s2++) p += s_prt[s2 * 32 + t];
        s_ms[t] = p;
    }
    __syncthreads();

    // ---- phase 3: hpart[c] = sum_r relu(P + bias_eff) ----
    {
        float be0 = b1v.x, be1 = b1v.y;
#pragma unroll
        for (int j = 0; j < CD; j++) {
            float mj = s_ms[j] * (1.0f / NA);
            float2 wv = *(const float2*)&s_s[j * HD + c0];   // W1 comm rows
            be0 += mj * wv.x;
            be1 += mj * wv.y;
        }
        float hp0 = 0.f, hp1 = 0.f;
#pragma unroll
        for (int rp = 0; rp < 4; rp++) {
            float x0, x1, y0, y1;
            unpack2(acc[rp][0], x0, x1);
            unpack2(acc[rp][1], y0, y1);
            hp0 += fmaxf(x0 + be0, 0.f) + fmaxf(x1 + be0, 0.f);
            hp1 += fmaxf(y0 + be1, 0.f) + fmaxf(y1 + be1, 0.f);
        }
        *(float2*)&s_prt[rg * HD + c0] = make_float2(hp0, hp1);
    }
    __syncthreads();
    if (t < HD) {
        float v = 0.f;
#pragma unroll
        for (int p = 0; p < 8; p++) v += s_prt[p * HD + t];
        g_hpart[bid * HD + t] = v;          // plain coalesced STG
    }

    bar_arrive(&g_barB);

    // ---- prefetch (hidden behind barB wait): W2 columns only ----
    int cc = t & 127, grp = t >> 7;   // 0..3, 32 k each
    float w2r[32];
#pragma unroll
    for (int i = 0; i < 32; i++) w2r[i] = W2[(grp * 32 + i) * HD + cc];

    bar_wait(&g_barB);

    // ---- parallel hsum reduction -> mean ----
    {
        float v = 0.f;
#pragma unroll 8
        for (int i = 0; i < 32; i++) v += g_hpart[(grp * 32 + i) * HD + cc];
        s_prt[grp * HD + cc] = v;
    }
    __syncthreads();
    if (t < HD) {
        float v = 0.f;
#pragma unroll
        for (int p = 0; p < 4; p++) v += s_prt[p * HD + t];
        s_mh[t] = v * (1.0f / NA);
    }
    __syncthreads();

    // ---- phase 4: g = relu((mean_h @ W2 + b2) @ Wg + bg) ----
    // GEMV1 uses prefetched w2r (split-K over 4 groups); GEMV2 warp-local.
    {
        float a = 0.f;
#pragma unroll
        for (int i = 0; i < 32; i++) a += s_mh[grp * 32 + i] * w2r[i];
        s_prt[grp * HD + cc] = a;
        __syncthreads();
        if (t < HD) {
            float v = b2[t];
#pragma unroll
            for (int p = 0; p < 4; p++) v += s_prt[p * HD + t];
            s_h2[t] = v;
        }
        __syncthreads();
        // GEMV2: warp w computes columns 8w..8w+7; lane-split-K (4 k per lane)
        float hk0 = s_h2[lane], hk1 = s_h2[lane + 32];
        float hk2 = s_h2[lane + 64], hk3 = s_h2[lane + 96];
#pragma unroll
        for (int j = 0; j < 8; j++) {
            int col = w * 8 + j;
            float d = hk0 * Wg[lane * HD + col] +
                      hk1 * Wg[(lane + 32) * HD + col] +
                      hk2 * Wg[(lane + 64) * HD + col] +
                      hk3 * Wg[(lane + 96) * HD + col];
#pragma unroll
            for (int o = 16; o; o >>= 1) d += __shfl_xor_sync(0xffffffffu, d, o);
            if (l == 0) s_g[col] = fmaxf(d + bg[col], 0.f);
        }
        __syncthreads();
    }

    // ---- phase 5: H = l2norm(g + 0.01*noise); heads. 4 rows per warp ----
    {
        float gp0 = s_g[lane +  0], gp1 = s_g[lane + 32];
        float gp2 = s_g[lane + 64], gp3 = s_g[lane + 96];
        float bpv = (lane < 8) ? bp[lane] : 0.f;
        float bvv = bv[0];
        float br0 = br[0], br1 = br[1], br2 = br[2];

#pragma unroll
        for (int i = 0; i < 4; i++) {
            int row = rowb + i;
            float v0 = gp0 + 0.01f * nz[i][0];
            float v1 = gp1 + 0.01f * nz[i][1];
            float v2 = gp2 + 0.01f * nz[i][2];
            float v3 = gp3 + 0.01f * nz[i][3];
            float ss = v0 * v0 + v1 * v1 + v2 * v2 + v3 * v3;
#pragma unroll
            for (int o = 16; o; o >>= 1) ss += __shfl_xor_sync(0xffffffffu, ss, o);
            float rn = 1.f / fmaxf(sqrtf(ss), 1e-12f);
            float h[4] = {v0 * rn, v1 * rn, v2 * rn, v3 * rn};

            float* oh = outH + (size_t)row * HD;
            oh[lane +  0] = h[0];
            oh[lane + 32] = h[1];
            oh[lane + 64] = h[2];
            oh[lane + 96] = h[3];

            float hd_[12];
#pragma unroll
            for (int j = 0; j < 12; j++) hd_[j] = 0.f;
#pragma unroll
            for (int m = 0; m < 4; m++) {
                int k = lane + 32 * m;
                const float4* wrow = (const float4*)&s_hw[k * 12];
                float4 wa = wrow[0], wb2 = wrow[1], wc2 = wrow[2];
                float hv = h[m];
                hd_[0] += hv * wa.x;  hd_[1] += hv * wa.y;
                hd_[2] += hv * wa.z;  hd_[3] += hv * wa.w;
                hd_[4] += hv * wb2.x; hd_[5] += hv * wb2.y;
                hd_[6] += hv * wb2.z; hd_[7] += hv * wb2.w;
                hd_[8] += hv * wc2.x; hd_[9] += hv * wc2.y;
                hd_[10] += hv * wc2.z; hd_[11] += hv * wc2.w;
            }
#pragma unroll
            for (int j = 0; j < 12; j++) {
#pragma unroll
                for (int o = 16; o; o >>= 1)
                    hd_[j] += __shfl_xor_sync(0xffffffffu, hd_[j], o);
            }

            if (lane < 8) {
                outA[(size_t)row * AD + lane] = tanhf(hd_[lane] + bpv);
            } else if (lane == 8) {
                outV[row] = hd_[8] + bvv;
            } else if (lane == 9) {
                float z0 = hd_[9] + br0, z1 = hd_[10] + br1, z2 = hd_[11] + br2;
                float mx = fmaxf(z0, fmaxf(z1, z2));
                float e0 = expf(z0 - mx), e1 = expf(z1 - mx), e2 = expf(z2 - mx);
                float inv = 1.f / (e0 + e1 + e2);
                outR[(size_t)row * 3 + 0] = e0 * inv;
                outR[(size_t)row * 3 + 1] = e1 * inv;
                outR[(size_t)row * 3 + 2] = e2 * inv;
            }
        }
    }

    // ---- epilogue: last CTA resets barrier counters for next graph replay ----
    __syncthreads();
    if (t == 0) {
        __threadfence();
        unsigned v = atomicAdd(&g_done, 1u);
        if (v == (unsigned)(NB - 1)) {
            g_barW = 0u; g_barA = 0u; g_barB = 0u;
            __threadfence();
            g_done = 0u;
        }
    }
}

#define FUSED_SMEM ((4096 + 8192 + 4096 + 32 + 32 + 128 + 128 + 128 + \
                     1024 + 1536) * 4)

extern "C" void kernel_launch(void* const* d_in, const int* in_sizes, int n_in,
                              void* d_out, int out_size) {
    const float* states = (const float*)d_in[0];
    const float* noise  = (const float*)d_in[1];
    const float* W1 = (const float*)d_in[2];
    const float* b1 = (const float*)d_in[3];
    const float* W2 = (const float*)d_in[4];
    const float* b2 = (const float*)d_in[5];
    const float* Wc = (const float*)d_in[6];
    const float* bc = (const float*)d_in[7];
    const float* Wg = (const float*)d_in[8];
    const float* bg = (const float*)d_in[9];
    const float* Wp = (const float*)d_in[10];
    const float* bp = (const float*)d_in[11];
    const float* Wv = (const float*)d_in[12];
    const float* bv = (const float*)d_in[13];
    const float* Wr = (const float*)d_in[14];
    const float* br = (const float*)d_in[15];

    float* outH = (float*)d_out;                       // [N, HD]
    float* outA = outH + (size_t)NA * HD;              // [N, AD]
    float* outV = outA + (size_t)NA * AD;              // [N, 1]
    float* outR = outV + (size_t)NA;                   // [N, 3]

    cudaFuncSetAttribute(kfused, cudaFuncAttributeMaxDynamicSharedMemorySize,
                         FUSED_SMEM);

    kfused<<<NB, NT, FUSED_SMEM>>>(states, noise, W1, b1, W2, b2, Wc, bc,
                                   Wg, bg, Wp, bp, Wv, bv, Wr, br,
                                   outH, outA, outV, outR);
}

// round 14
// speedup vs baseline: 1.3174x; 1.3174x over previous
#include <cuda_runtime.h>
#include <math.h>

#define NA 8192
#define SD 64
#define HD 128
#define CD 32
#define AD 8
#define NB 128
#define NT 512
#define ROWS 64

// -------- device scratch (zero-initialized; kernel self-resets counters) ----
__device__ float g_W2c[HD * CD];        // K-major: [k][c]
__device__ float g_bc2[CD];
__device__ float g_msgpart[NB * CD];    // per-CTA msum partials
__device__ float g_hpart[NB * HD];      // per-CTA hsum partials
__device__ unsigned g_barW, g_barA, g_barB, g_done;

typedef unsigned long long ull;

__device__ __forceinline__ ull pack2(float lo, float hi) {
    ull r;
    asm("mov.b64 %0, {%1, %2};" : "=l"(r) : "f"(lo), "f"(hi));
    return r;
}
__device__ __forceinline__ void unpack2(ull v, float& lo, float& hi) {
    asm("mov.b64 {%0, %1}, %2;" : "=f"(lo), "=f"(hi) : "l"(v));
}
__device__ __forceinline__ ull fma2(ull a, ull b, ull c) {
    ull d;
    asm("fma.rn.f32x2 %0, %1, %2, %3;" : "=l"(d) : "l"(a), "l"(b), "l"(c));
    return d;
}

// ---- split grid barrier: release-arrive / acquire-wait ----
__device__ __forceinline__ void bar_arrive(unsigned* ctr) {
    __syncthreads();
    if (threadIdx.x == 0)
        asm volatile("red.release.gpu.global.add.u32 [%0], 1;"
                     :: "l"(ctr) : "memory");
}
__device__ __forceinline__ void bar_wait(unsigned* ctr) {
    if (threadIdx.x == 0) {
        unsigned v;
        do {
            asm volatile("ld.acquire.gpu.global.u32 %0, [%1];"
                         : "=r"(v) : "l"(ctr) : "memory");
        } while (v < (unsigned)NB);
    }
    __syncthreads();
}

__global__ void __launch_bounds__(NT, 1) kfused(
    const float* __restrict__ states, const float* __restrict__ noise,
    const float* __restrict__ W1, const float* __restrict__ b1,
    const float* __restrict__ W2, const float* __restrict__ b2,
    const float* __restrict__ Wc, const float* __restrict__ bc,
    const float* __restrict__ Wg, const float* __restrict__ bg,
    const float* __restrict__ Wp, const float* __restrict__ bp,
    const float* __restrict__ Wv, const float* __restrict__ bv,
    const float* __restrict__ Wr, const float* __restrict__ br,
    float* __restrict__ outH, float* __restrict__ outA,
    float* __restrict__ outV, float* __restrict__ outR) {

    extern __shared__ float sm[];
    float* s_s   = sm;              // 4096: states row-interleaved; later W1comm
    float* s_wh  = s_s + 4096;      // 8192: W1[0:64][128]; later h[64][128]
    float* s_w2c = s_wh + 8192;     // 4096: W2c K-major [k][32]
    float* s_ms  = s_w2c + 4096;    // 32
    float* s_bc2 = s_ms + 32;       // 32
    float* s_mh  = s_bc2 + 32;      // 128
    float* s_h2  = s_mh + 128;      // 128
    float* s_g   = s_h2 + 128;      // 128
    float* s_prt = s_g + 128;       // 8*128 = 1024
    float* s_hw  = s_prt + 1024;    // 1536  head weights [k][12]

    int t = threadIdx.x;
    int bid = blockIdx.x;
    int r0 = bid * ROWS;
    int w = t >> 5, l = t & 31;

    // ---- distributed W2c fold: 2 dots per warp ----
    {
#pragma unroll
        for (int e = 0; e < 2; e++) {
            int idx = bid * 32 + w * 2 + e;        // 0..4095
            int c = idx & 31, k = idx >> 5;
            float4 w2v = *(const float4*)&W2[k * HD + l * 4];
            float d = w2v.x * Wc[(l * 4 + 0) * CD + c] +
                      w2v.y * Wc[(l * 4 + 1) * CD + c] +
                      w2v.z * Wc[(l * 4 + 2) * CD + c] +
                      w2v.w * Wc[(l * 4 + 3) * CD + c];
#pragma unroll
            for (int o = 16; o; o >>= 1) d += __shfl_xor_sync(0xffffffffu, d, o);
            if (l == 0) g_W2c[k * CD + c] = d;
        }
        if (bid == 1) {
#pragma unroll
            for (int e = 0; e < 2; e++) {
                int c = w * 2 + e;
                float4 b2v = *(const float4*)&b2[l * 4];
                float d = b2v.x * Wc[(l * 4 + 0) * CD + c] +
                          b2v.y * Wc[(l * 4 + 1) * CD + c] +
                          b2v.z * Wc[(l * 4 + 2) * CD + c] +
                          b2v.w * Wc[(l * 4 + 3) * CD + c];
#pragma unroll
                for (int o = 16; o; o >>= 1) d += __shfl_xor_sync(0xffffffffu, d, o);
                if (l == 0) g_bc2[c] = d + bc[c];
            }
        }
    }

    bar_arrive(&g_barW);    // W2c/bc2 published; wait deferred past phase 1

    // ---- stage: states (coalesced LDG.128 -> interleaved STS), W1[0:64],
    //      head weights (row-per-thread, coalesced) ----
#pragma unroll
    for (int ii = 0; ii < 2; ii++) {
        int i = t + ii * NT;          // 0..1023 : one float4 of one state row
        int row = i >> 4;             // 16 float4 per row
        int k4 = i & 15;
        float4 v = ((const float4*)(states + (size_t)(r0 + row) * SD))[k4];
        int rp = row >> 1, sub = row & 1;
        float* dst = &s_s[rp * 128 + sub];
        dst[(4 * k4 + 0) * 2] = v.x;
        dst[(4 * k4 + 1) * 2] = v.y;
        dst[(4 * k4 + 2) * 2] = v.z;
        dst[(4 * k4 + 3) * 2] = v.w;
    }
    ((float4*)s_wh)[t]        = ((const float4*)W1)[t];
    ((float4*)s_wh)[t +  512] = ((const float4*)W1)[t +  512];
    ((float4*)s_wh)[t + 1024] = ((const float4*)W1)[t + 1024];
    ((float4*)s_wh)[t + 1536] = ((const float4*)W1)[t + 1536];
    if (t < HD) {
        int k = t;
        const float4* wp4 = (const float4*)&Wp[k * AD];
        float4 pa = wp4[0], pb = wp4[1];
        float vv = Wv[k];
        float r0v = Wr[k * 3], r1v = Wr[k * 3 + 1], r2v = Wr[k * 3 + 2];
        float* dst = &s_hw[k * 12];
        dst[0] = pa.x; dst[1] = pa.y; dst[2] = pa.z; dst[3] = pa.w;
        dst[4] = pb.x; dst[5] = pb.y; dst[6] = pb.z; dst[7] = pb.w;
        dst[8] = vv;   dst[9] = r0v;  dst[10] = r1v; dst[11] = r2v;
    }
    __syncthreads();

    // ---- phase 1: P = states @ W1[:64], packed row-pairs (FFMA2) ----
    int c0 = (t & 63) * 2;
    int rg = t >> 6;              // 0..7 -> rows rg*8 .. rg*8+7
    int rp0 = rg * 4;             // 4 row-pairs
    float2 b1v = *(const float2*)&b1[c0];
    ull acc[4][2];
#pragma unroll
    for (int r = 0; r < 4; r++) { acc[r][0] = 0ull; acc[r][1] = 0ull; }

#pragma unroll 4
    for (int k = 0; k < SD; k += 4) {
        float2 wv0 = *(const float2*)&s_wh[(k + 0) * HD + c0];
        float2 wv1 = *(const float2*)&s_wh[(k + 1) * HD + c0];
        float2 wv2 = *(const float2*)&s_wh[(k + 2) * HD + c0];
        float2 wv3 = *(const float2*)&s_wh[(k + 3) * HD + c0];
        ull w00 = pack2(wv0.x, wv0.x), w01 = pack2(wv0.y, wv0.y);
        ull w10 = pack2(wv1.x, wv1.x), w11 = pack2(wv1.y, wv1.y);
        ull w20 = pack2(wv2.x, wv2.x), w21 = pack2(wv2.y, wv2.y);
        ull w30 = pack2(wv3.x, wv3.x), w31 = pack2(wv3.y, wv3.y);
#pragma unroll
        for (int rp = 0; rp < 4; rp++) {
            ulonglong2 sa = *(const ulonglong2*)&s_s[(rp0 + rp) * 128 + k * 2];
            ulonglong2 sb = *(const ulonglong2*)&s_s[(rp0 + rp) * 128 + k * 2 + 4];
            acc[rp][0] = fma2(sa.x, w00, acc[rp][0]);
            acc[rp][1] = fma2(sa.x, w01, acc[rp][1]);
            acc[rp][0] = fma2(sa.y, w10, acc[rp][0]);
            acc[rp][1] = fma2(sa.y, w11, acc[rp][1]);
            acc[rp][0] = fma2(sb.x, w20, acc[rp][0]);
            acc[rp][1] = fma2(sb.x, w21, acc[rp][1]);
            acc[rp][0] = fma2(sb.y, w30, acc[rp][0]);
            acc[rp][1] = fma2(sb.y, w31, acc[rp][1]);
        }
    }
    __syncthreads();   // all W1/states reads complete

    // h = relu(P+b1) -> s_wh (reuse); stage W1 comm rows -> s_s (reuse)
#pragma unroll
    for (int rp = 0; rp < 4; rp++) {
        float x0, x1, y0, y1;
        unpack2(acc[rp][0], x0, x1);
        unpack2(acc[rp][1], y0, y1);
        int rowe = 2 * (rp0 + rp);
        *(float2*)&s_wh[rowe * HD + c0] =
            make_float2(fmaxf(x0 + b1v.x, 0.f), fmaxf(y0 + b1v.y, 0.f));
        *(float2*)&s_wh[(rowe + 1) * HD + c0] =
            make_float2(fmaxf(x1 + b1v.x, 0.f), fmaxf(y1 + b1v.y, 0.f));
    }
    ((float4*)s_s)[t]       = ((const float4*)(W1 + SD * HD))[t];
    ((float4*)s_s)[t + 512] = ((const float4*)(W1 + SD * HD))[t + 512];

    bar_wait(&g_barW);   // hidden behind phase 1

    // stage W2c (K-major) + bc2
    ((float4*)s_w2c)[t]       = ((const float4*)g_W2c)[t];
    ((float4*)s_w2c)[t + 512] = ((const float4*)g_W2c)[t + 512];
    if (t < CD) s_bc2[t] = g_bc2[t];
    __syncthreads();

    // ---- phase 2: msgs = l2norm(h @ W2c + bc2), all-warp-local reduction ----
    {
        int rrA = t >> 4;              // 0..31; also handles rrA+32
        int mcp = (t & 15) * 2;
        ull mA = *(const ull*)&s_bc2[mcp];
        ull mB = mA;
#pragma unroll 4
        for (int k = 0; k < HD; k += 4) {
            float4 hA = *(const float4*)&s_wh[rrA * HD + k];
            float4 hB = *(const float4*)&s_wh[(rrA + 32) * HD + k];
            ull wv0 = *(const ull*)&s_w2c[(k + 0) * CD + mcp];
            ull wv1 = *(const ull*)&s_w2c[(k + 1) * CD + mcp];
            ull wv2 = *(const ull*)&s_w2c[(k + 2) * CD + mcp];
            ull wv3 = *(const ull*)&s_w2c[(k + 3) * CD + mcp];
            mA = fma2(pack2(hA.x, hA.x), wv0, mA);
            mB = fma2(pack2(hB.x, hB.x), wv0, mB);
            mA = fma2(pack2(hA.y, hA.y), wv1, mA);
            mB = fma2(pack2(hB.y, hB.y), wv1, mB);
            mA = fma2(pack2(hA.z, hA.z), wv2, mA);
            mB = fma2(pack2(hB.z, hB.z), wv2, mB);
            mA = fma2(pack2(hA.w, hA.w), wv3, mA);
            mB = fma2(pack2(hB.w, hB.w), wv3, mB);
        }
        float a0, a1, b0v, b1x;
        unpack2(mA, a0, a1);
        unpack2(mB, b0v, b1x);
        float ssA = a0 * a0 + a1 * a1;
        float ssB = b0v * b0v + b1x * b1x;
#pragma unroll
        for (int o = 1; o <= 8; o <<= 1) {
            ssA += __shfl_xor_sync(0xffffffffu, ssA, o);
            ssB += __shfl_xor_sync(0xffffffffu, ssB, o);
        }
        float rnA = 1.f / fmaxf(sqrtf(ssA), 1e-12f);
        float rnB = 1.f / fmaxf(sqrtf(ssB), 1e-12f);
        float p0 = a0 * rnA + b0v * rnB;
        float p1 = a1 * rnA + b1x * rnB;
        p0 += __shfl_xor_sync(0xffffffffu, p0, 16);
        p1 += __shfl_xor_sync(0xffffffffu, p1, 16);
        if (l < 16) *(float2*)&s_prt[w * 32 + mcp] = make_float2(p0, p1);
    }
    __syncthreads();
    if (t < CD) {
        float p = 0.f;
#pragma unroll
        for (int w2 = 0; w2 < 16; w2++) p += s_prt[w2 * 32 + t];
        g_msgpart[bid * CD + t] = p;        // plain coalesced STG
    }

    bar_arrive(&g_barA);

    // ---- noise prefetch fills the barA gap ----
    int w5 = t >> 5, lane = t & 31;
    int rowb = r0 + w5 * 4;
    const float* nb = noise + (size_t)rowb * HD;
    float nz[4][4];
#pragma unroll
    for (int i = 0; i < 4; i++) {
        nz[i][0] = nb[i * HD + lane +  0];
        nz[i][1] = nb[i * HD + lane + 32];
        nz[i][2] = nb[i * HD + lane + 64];
        nz[i][3] = nb[i * HD + lane + 96];
    }

    bar_wait(&g_barA);

    // ---- parallel msum reduction ----
    {
        int c = t & 31, seg = t >> 5;       // 16 segs x 8 CTAs
        float p = 0.f;
#pragma unroll
        for (int i = 0; i < 8; i++) p += g_msgpart[(seg * 8 + i) * CD + c];
        s_prt[seg * 32 + c] = p;
    }
    __syncthreads();
    if (t < CD) {
        float p = 0.f;
#pragma unroll
        for (int s2 = 0; s2 < 16; s2++) p += s_prt[s2 * 32 + t];
        s_ms[t] = p;
    }
    __syncthreads();

    // ---- phase 3: hpart[c] = sum_r relu(P + bias_eff) ----
    {
        float be0 = b1v.x, be1 = b1v.y;
#pragma unroll
        for (int j = 0; j < CD; j++) {
            float mj = s_ms[j] * (1.0f / NA);
            float2 wv = *(const float2*)&s_s[j * HD + c0];   // W1 comm rows
            be0 += mj * wv.x;
            be1 += mj * wv.y;
        }
        float hp0 = 0.f, hp1 = 0.f;
#pragma unroll
        for (int rp = 0; rp < 4; rp++) {
            float x0, x1, y0, y1;
            unpack2(acc[rp][0], x0, x1);
            unpack2(acc[rp][1], y0, y1);
            hp0 += fmaxf(x0 + be0, 0.f) + fmaxf(x1 + be0, 0.f);
            hp1 += fmaxf(y0 + be1, 0.f) + fmaxf(y1 + be1, 0.f);
        }
        *(float2*)&s_prt[rg * HD + c0] = make_float2(hp0, hp1);
    }
    __syncthreads();
    if (t < HD) {
        float v = 0.f;
#pragma unroll
        for (int p = 0; p < 8; p++) v += s_prt[p * HD + t];
        g_hpart[bid * HD + t] = v;          // plain coalesced STG
    }

    bar_arrive(&g_barB);

    // ---- prefetch (hidden behind barB wait): W2 columns only ----
    int cc = t & 127, grp = t >> 7;   // 0..3, 32 k each
    float w2r[32];
#pragma unroll
    for (int i = 0; i < 32; i++) w2r[i] = W2[(grp * 32 + i) * HD + cc];

    bar_wait(&g_barB);

    // ---- parallel hsum reduction -> mean ----
    {
        float v = 0.f;
#pragma unroll 8
        for (int i = 0; i < 32; i++) v += g_hpart[(grp * 32 + i) * HD + cc];
        s_prt[grp * HD + cc] = v;
    }
    __syncthreads();
    if (t < HD) {
        float v = 0.f;
#pragma unroll
        for (int p = 0; p < 4; p++) v += s_prt[p * HD + t];
        s_mh[t] = v * (1.0f / NA);
    }
    __syncthreads();

    // ---- phase 4: g = relu((mean_h @ W2 + b2) @ Wg + bg) ----
    {
        float a = 0.f;
#pragma unroll
        for (int i = 0; i < 32; i++) a += s_mh[grp * 32 + i] * w2r[i];
        s_prt[grp * HD + cc] = a;
        __syncthreads();
        if (t < HD) {
            float v = b2[t];
#pragma unroll
            for (int p = 0; p < 4; p++) v += s_prt[p * HD + t];
            s_h2[t] = v;
        }
        __syncthreads();
        float g2 = 0.f;
#pragma unroll
        for (int seg = 0; seg < 2; seg++) {
            float wgr[16];
#pragma unroll
            for (int i = 0; i < 16; i++)
                wgr[i] = Wg[(grp * 32 + seg * 16 + i) * HD + cc];
#pragma unroll
            for (int i = 0; i < 16; i++)
                g2 += s_h2[grp * 32 + seg * 16 + i] * wgr[i];
        }
        s_prt[grp * HD + cc] = g2;
        __syncthreads();
        if (t < HD) {
            float v = bg[t];
#pragma unroll
            for (int p = 0; p < 4; p++) v += s_prt[p * HD + t];
            s_g[t] = fmaxf(v, 0.f);
        }
        __syncthreads();
    }

    // ---- phase 5: H = l2norm(g + 0.01*noise); heads. 4 rows per warp ----
    {
        float gp0 = s_g[lane +  0], gp1 = s_g[lane + 32];
        float gp2 = s_g[lane + 64], gp3 = s_g[lane + 96];
        float bpv = (lane < 8) ? bp[lane] : 0.f;
        float bvv = bv[0];
        float br0 = br[0], br1 = br[1], br2 = br[2];

#pragma unroll
        for (int i = 0; i < 4; i++) {
            int row = rowb + i;
            float v0 = gp0 + 0.01f * nz[i][0];
            float v1 = gp1 + 0.01f * nz[i][1];
            float v2 = gp2 + 0.01f * nz[i][2];
            float v3 = gp3 + 0.01f * nz[i][3];
            float ss = v0 * v0 + v1 * v1 + v2 * v2 + v3 * v3;
#pragma unroll
            for (int o = 16; o; o >>= 1) ss += __shfl_xor_sync(0xffffffffu, ss, o);
            float rn = 1.f / fmaxf(sqrtf(ss), 1e-12f);
            float h[4] = {v0 * rn, v1 * rn, v2 * rn, v3 * rn};

            float* oh = outH + (size_t)row * HD;
            oh[lane +  0] = h[0];
            oh[lane + 32] = h[1];
            oh[lane + 64] = h[2];
            oh[lane + 96] = h[3];

            float hd_[12];
#pragma unroll
            for (int j = 0; j < 12; j++) hd_[j] = 0.f;
#pragma unroll
            for (int m = 0; m < 4; m++) {
                int k = lane + 32 * m;
                const float4* wrow = (const float4*)&s_hw[k * 12];
                float4 wa = wrow[0], wb2 = wrow[1], wc2 = wrow[2];
                float hv = h[m];
                hd_[0] += hv * wa.x;  hd_[1] += hv * wa.y;
                hd_[2] += hv * wa.z;  hd_[3] += hv * wa.w;
                hd_[4] += hv * wb2.x; hd_[5] += hv * wb2.y;
                hd_[6] += hv * wb2.z; hd_[7] += hv * wb2.w;
                hd_[8] += hv * wc2.x; hd_[9] += hv * wc2.y;
                hd_[10] += hv * wc2.z; hd_[11] += hv * wc2.w;
            }
#pragma unroll
            for (int j = 0; j < 12; j++) {
#pragma unroll
                for (int o = 16; o; o >>= 1)
                    hd_[j] += __shfl_xor_sync(0xffffffffu, hd_[j], o);
            }

            if (lane < 8) {
                outA[(size_t)row * AD + lane] = tanhf(hd_[lane] + bpv);
            } else if (lane == 8) {
                outV[row] = hd_[8] + bvv;
            } else if (lane == 9) {
                float z0 = hd_[9] + br0, z1 = hd_[10] + br1, z2 = hd_[11] + br2;
                float mx = fmaxf(z0, fmaxf(z1, z2));
                float e0 = expf(z0 - mx), e1 = expf(z1 - mx), e2 = expf(z2 - mx);
                float inv = 1.f / (e0 + e1 + e2);
                outR[(size_t)row * 3 + 0] = e0 * inv;
                outR[(size_t)row * 3 + 1] = e1 * inv;
                outR[(size_t)row * 3 + 2] = e2 * inv;
            }
        }
    }

    // ---- epilogue: last CTA resets barrier counters for next graph replay ----
    __syncthreads();
    if (t == 0) {
        __threadfence();
        unsigned v = atomicAdd(&g_done, 1u);
        if (v == (unsigned)(NB - 1)) {
            g_barW = 0u; g_barA = 0u; g_barB = 0u;
            __threadfence();
            g_done = 0u;
        }
    }
}

#define FUSED_SMEM ((4096 + 8192 + 4096 + 32 + 32 + 128 + 128 + 128 + \
                     1024 + 1536) * 4)

extern "C" void kernel_launch(void* const* d_in, const int* in_sizes, int n_in,
                              void* d_out, int out_size) {
    const float* states = (const float*)d_in[0];
    const float* noise  = (const float*)d_in[1];
    const float* W1 = (const float*)d_in[2];
    const float* b1 = (const float*)d_in[3];
    const float* W2 = (const float*)d_in[4];
    const float* b2 = (const float*)d_in[5];
    const float* Wc = (const float*)d_in[6];
    const float* bc = (const float*)d_in[7];
    const float* Wg = (const float*)d_in[8];
    const float* bg = (const float*)d_in[9];
    const float* Wp = (const float*)d_in[10];
    const float* bp = (const float*)d_in[11];
    const float* Wv = (const float*)d_in[12];
    const float* bv = (const float*)d_in[13];
    const float* Wr = (const float*)d_in[14];
    const float* br = (const float*)d_in[15];

    float* outH = (float*)d_out;                       // [N, HD]
    float* outA = outH + (size_t)NA * HD;              // [N, AD]
    float* outV = outA + (size_t)NA * AD;              // [N, 1]
    float* outR = outV + (size_t)NA;                   // [N, 3]

    cudaFuncSetAttribute(kfused, cudaFuncAttributeMaxDynamicSharedMemorySize,
                         FUSED_SMEM);

    kfused<<<NB, NT, FUSED_SMEM>>>(states, noise, W1, b1, W2, b2, Wc, bc,
                                   Wg, bg, Wp, bp, Wv, bv, Wr, br,
                                   outH, outA, outV, outR);
}

// round 15
// speedup vs baseline: 1.5344x; 1.1647x over previous
#include <cuda_runtime.h>
#include <math.h>

#define NA 8192
#define SD 64
#define HD 128
#define CD 32
#define AD 8
#define NB 128
#define NT 512
#define ROWS 64

// -------- device scratch (zero-initialized; kernel self-resets counters) ----
__device__ float g_W2c[HD * CD];        // K-major: [k][c]
__device__ float g_bc2[CD];
__device__ float g_msgpart[NB * CD];    // per-CTA msum partials
__device__ float g_hpart[NB * HD];      // per-CTA hsum partials
__device__ unsigned g_barW, g_barA, g_barB, g_done;

typedef unsigned long long ull;

__device__ __forceinline__ ull pack2(float lo, float hi) {
    ull r;
    asm("mov.b64 %0, {%1, %2};" : "=l"(r) : "f"(lo), "f"(hi));
    return r;
}
__device__ __forceinline__ void unpack2(ull v, float& lo, float& hi) {
    asm("mov.b64 {%0, %1}, %2;" : "=f"(lo), "=f"(hi) : "l"(v));
}
__device__ __forceinline__ ull fma2(ull a, ull b, ull c) {
    ull d;
    asm("fma.rn.f32x2 %0, %1, %2, %3;" : "=l"(d) : "l"(a), "l"(b), "l"(c));
    return d;
}

// ---- split grid barrier: release-arrive / acquire-wait ----
__device__ __forceinline__ void bar_arrive(unsigned* ctr) {
    __syncthreads();
    if (threadIdx.x == 0)
        asm volatile("red.release.gpu.global.add.u32 [%0], 1;"
                     :: "l"(ctr) : "memory");
}
__device__ __forceinline__ void bar_wait(unsigned* ctr) {
    if (threadIdx.x == 0) {
        unsigned v;
        do {
            asm volatile("ld.acquire.gpu.global.u32 %0, [%1];"
                         : "=r"(v) : "l"(ctr) : "memory");
        } while (v < (unsigned)NB);
    }
    __syncthreads();
}

__global__ void __launch_bounds__(NT, 1) kfused(
    const float* __restrict__ states, const float* __restrict__ noise,
    const float* __restrict__ W1, const float* __restrict__ b1,
    const float* __restrict__ W2, const float* __restrict__ b2,
    const float* __restrict__ Wc, const float* __restrict__ bc,
    const float* __restrict__ Wg, const float* __restrict__ bg,
    const float* __restrict__ Wp, const float* __restrict__ bp,
    const float* __restrict__ Wv, const float* __restrict__ bv,
    const float* __restrict__ Wr, const float* __restrict__ br,
    float* __restrict__ outH, float* __restrict__ outA,
    float* __restrict__ outV, float* __restrict__ outR) {

    extern __shared__ float sm[];
    float* s_s   = sm;              // 4096: states row-interleaved; later W1comm
    float* s_wh  = s_s + 4096;      // 8192: W1[0:64][128]; later h[64][128]
    float* s_w2c = s_wh + 8192;     // 4096: W2c K-major [k][32]
    float* s_ms  = s_w2c + 4096;    // 32
    float* s_bc2 = s_ms + 32;       // 32
    float* s_mh  = s_bc2 + 32;      // 128
    float* s_h2  = s_mh + 128;      // 128
    float* s_g   = s_h2 + 128;      // 128
    float* s_prt = s_g + 128;       // 8*128 = 1024
    float* s_hw  = s_prt + 1024;    // 1536  head weights [k][12]

    int t = threadIdx.x;
    int bid = blockIdx.x;
    int r0 = bid * ROWS;
    int w = t >> 5, l = t & 31;

    // ---- W2c fold, warp-per-k-row (coalesced Wc): CTA bid owns row k=bid ----
    {
        float a = 0.f;
#pragma unroll
        for (int j8 = 0; j8 < 8; j8++) {
            int j = w * 8 + j8;
            a += W2[bid * HD + j] * Wc[j * CD + l];   // broadcast * coalesced
        }
        s_prt[w * 32 + l] = a;
        if (bid == 0) {                                // bc2 partials
            float b = 0.f;
#pragma unroll
            for (int j8 = 0; j8 < 8; j8++) {
                int j = w * 8 + j8;
                b += b2[j] * Wc[j * CD + l];
            }
            s_prt[512 + w * 32 + l] = b;
        }
    }
    __syncthreads();
    if (t < CD) {
        float a = 0.f;
#pragma unroll
        for (int w2 = 0; w2 < 16; w2++) a += s_prt[w2 * 32 + t];
        g_W2c[bid * CD + t] = a;
    } else if (bid == 0 && t >= 32 && t < 64) {
        int c = t - 32;
        float b = 0.f;
#pragma unroll
        for (int w2 = 0; w2 < 16; w2++) b += s_prt[512 + w2 * 32 + c];
        g_bc2[c] = b + bc[c];
    }

    bar_arrive(&g_barW);    // W2c/bc2 published; wait deferred past phase 1

    // ---- stage: states (coalesced LDG.128 -> interleaved STS), W1[0:64],
    //      head weights (row-per-thread, coalesced) ----
#pragma unroll
    for (int ii = 0; ii < 2; ii++) {
        int i = t + ii * NT;          // 0..1023 : one float4 of one state row
        int row = i >> 4;             // 16 float4 per row
        int k4 = i & 15;
        float4 v = ((const float4*)(states + (size_t)(r0 + row) * SD))[k4];
        int rp = row >> 1, sub = row & 1;
        float* dst = &s_s[rp * 128 + sub];
        dst[(4 * k4 + 0) * 2] = v.x;
        dst[(4 * k4 + 1) * 2] = v.y;
        dst[(4 * k4 + 2) * 2] = v.z;
        dst[(4 * k4 + 3) * 2] = v.w;
    }
    ((float4*)s_wh)[t]        = ((const float4*)W1)[t];
    ((float4*)s_wh)[t +  512] = ((const float4*)W1)[t +  512];
    ((float4*)s_wh)[t + 1024] = ((const float4*)W1)[t + 1024];
    ((float4*)s_wh)[t + 1536] = ((const float4*)W1)[t + 1536];
    if (t < HD) {
        int k = t;
        const float4* wp4 = (const float4*)&Wp[k * AD];
        float4 pa = wp4[0], pb = wp4[1];
        float vv = Wv[k];
        float r0v = Wr[k * 3], r1v = Wr[k * 3 + 1], r2v = Wr[k * 3 + 2];
        float* dst = &s_hw[k * 12];
        dst[0] = pa.x; dst[1] = pa.y; dst[2] = pa.z; dst[3] = pa.w;
        dst[4] = pb.x; dst[5] = pb.y; dst[6] = pb.z; dst[7] = pb.w;
        dst[8] = vv;   dst[9] = r0v;  dst[10] = r1v; dst[11] = r2v;
    }
    __syncthreads();

    // ---- phase 1: P = states @ W1[:64], packed row-pairs (FFMA2) ----
    int c0 = (t & 63) * 2;
    int rg = t >> 6;              // 0..7 -> rows rg*8 .. rg*8+7
    int rp0 = rg * 4;             // 4 row-pairs
    float2 b1v = *(const float2*)&b1[c0];
    ull acc[4][2];
#pragma unroll
    for (int r = 0; r < 4; r++) { acc[r][0] = 0ull; acc[r][1] = 0ull; }

#pragma unroll 4
    for (int k = 0; k < SD; k += 4) {
        float2 wv0 = *(const float2*)&s_wh[(k + 0) * HD + c0];
        float2 wv1 = *(const float2*)&s_wh[(k + 1) * HD + c0];
        float2 wv2 = *(const float2*)&s_wh[(k + 2) * HD + c0];
        float2 wv3 = *(const float2*)&s_wh[(k + 3) * HD + c0];
        ull w00 = pack2(wv0.x, wv0.x), w01 = pack2(wv0.y, wv0.y);
        ull w10 = pack2(wv1.x, wv1.x), w11 = pack2(wv1.y, wv1.y);
        ull w20 = pack2(wv2.x, wv2.x), w21 = pack2(wv2.y, wv2.y);
        ull w30 = pack2(wv3.x, wv3.x), w31 = pack2(wv3.y, wv3.y);
#pragma unroll
        for (int rp = 0; rp < 4; rp++) {
            ulonglong2 sa = *(const ulonglong2*)&s_s[(rp0 + rp) * 128 + k * 2];
            ulonglong2 sb = *(const ulonglong2*)&s_s[(rp0 + rp) * 128 + k * 2 + 4];
            acc[rp][0] = fma2(sa.x, w00, acc[rp][0]);
            acc[rp][1] = fma2(sa.x, w01, acc[rp][1]);
            acc[rp][0] = fma2(sa.y, w10, acc[rp][0]);
            acc[rp][1] = fma2(sa.y, w11, acc[rp][1]);
            acc[rp][0] = fma2(sb.x, w20, acc[rp][0]);
            acc[rp][1] = fma2(sb.x, w21, acc[rp][1]);
            acc[rp][0] = fma2(sb.y, w30, acc[rp][0]);
            acc[rp][1] = fma2(sb.y, w31, acc[rp][1]);
        }
    }
    __syncthreads();   // all W1/states reads complete

    // h = relu(P+b1) -> s_wh (reuse); stage W1 comm rows -> s_s (reuse)
#pragma unroll
    for (int rp = 0; rp < 4; rp++) {
        float x0, x1, y0, y1;
        unpack2(acc[rp][0], x0, x1);
        unpack2(acc[rp][1], y0, y1);
        int rowe = 2 * (rp0 + rp);
        *(float2*)&s_wh[rowe * HD + c0] =
            make_float2(fmaxf(x0 + b1v.x, 0.f), fmaxf(y0 + b1v.y, 0.f));
        *(float2*)&s_wh[(rowe + 1) * HD + c0] =
            make_float2(fmaxf(x1 + b1v.x, 0.f), fmaxf(y1 + b1v.y, 0.f));
    }
    ((float4*)s_s)[t]       = ((const float4*)(W1 + SD * HD))[t];
    ((float4*)s_s)[t + 512] = ((const float4*)(W1 + SD * HD))[t + 512];

    bar_wait(&g_barW);   // hidden behind phase 1

    // stage W2c (K-major) + bc2
    ((float4*)s_w2c)[t]       = ((const float4*)g_W2c)[t];
    ((float4*)s_w2c)[t + 512] = ((const float4*)g_W2c)[t + 512];
    if (t < CD) s_bc2[t] = g_bc2[t];
    __syncthreads();

    // ---- phase 2: msgs = l2norm(h @ W2c + bc2), all-warp-local reduction ----
    {
        int rrA = t >> 4;              // 0..31; also handles rrA+32
        int mcp = (t & 15) * 2;
        ull mA = *(const ull*)&s_bc2[mcp];
        ull mB = mA;
#pragma unroll 4
        for (int k = 0; k < HD; k += 4) {
            float4 hA = *(const float4*)&s_wh[rrA * HD + k];
            float4 hB = *(const float4*)&s_wh[(rrA + 32) * HD + k];
            ull wv0 = *(const ull*)&s_w2c[(k + 0) * CD + mcp];
            ull wv1 = *(const ull*)&s_w2c[(k + 1) * CD + mcp];
            ull wv2 = *(const ull*)&s_w2c[(k + 2) * CD + mcp];
            ull wv3 = *(const ull*)&s_w2c[(k + 3) * CD + mcp];
            mA = fma2(pack2(hA.x, hA.x), wv0, mA);
            mB = fma2(pack2(hB.x, hB.x), wv0, mB);
            mA = fma2(pack2(hA.y, hA.y), wv1, mA);
            mB = fma2(pack2(hB.y, hB.y), wv1, mB);
            mA = fma2(pack2(hA.z, hA.z), wv2, mA);
            mB = fma2(pack2(hB.z, hB.z), wv2, mB);
            mA = fma2(pack2(hA.w, hA.w), wv3, mA);
            mB = fma2(pack2(hB.w, hB.w), wv3, mB);
        }
        float a0, a1, b0v, b1x;
        unpack2(mA, a0, a1);
        unpack2(mB, b0v, b1x);
        float ssA = a0 * a0 + a1 * a1;
        float ssB = b0v * b0v + b1x * b1x;
#pragma unroll
        for (int o = 1; o <= 8; o <<= 1) {
            ssA += __shfl_xor_sync(0xffffffffu, ssA, o);
            ssB += __shfl_xor_sync(0xffffffffu, ssB, o);
        }
        float rnA = 1.f / fmaxf(sqrtf(ssA), 1e-12f);
        float rnB = 1.f / fmaxf(sqrtf(ssB), 1e-12f);
        float p0 = a0 * rnA + b0v * rnB;
        float p1 = a1 * rnA + b1x * rnB;
        p0 += __shfl_xor_sync(0xffffffffu, p0, 16);
        p1 += __shfl_xor_sync(0xffffffffu, p1, 16);
        if (l < 16) *(float2*)&s_prt[w * 32 + mcp] = make_float2(p0, p1);
    }
    __syncthreads();
    if (t < CD) {
        float p = 0.f;
#pragma unroll
        for (int w2 = 0; w2 < 16; w2++) p += s_prt[w2 * 32 + t];
        g_msgpart[bid * CD + t] = p;        // plain coalesced STG
    }

    bar_arrive(&g_barA);

    // ---- noise prefetch fills the barA gap ----
    int w5 = t >> 5, lane = t & 31;
    int rowb = r0 + w5 * 4;
    const float* nb = noise + (size_t)rowb * HD;
    float nz[4][4];
#pragma unroll
    for (int i = 0; i < 4; i++) {
        nz[i][0] = nb[i * HD + lane +  0];
        nz[i][1] = nb[i * HD + lane + 32];
        nz[i][2] = nb[i * HD + lane + 64];
        nz[i][3] = nb[i * HD + lane + 96];
    }

    bar_wait(&g_barA);

    // ---- parallel msum reduction ----
    {
        int c = t & 31, seg = t >> 5;       // 16 segs x 8 CTAs
        float p = 0.f;
#pragma unroll
        for (int i = 0; i < 8; i++) p += g_msgpart[(seg * 8 + i) * CD + c];
        s_prt[seg * 32 + c] = p;
    }
    __syncthreads();
    if (t < CD) {
        float p = 0.f;
#pragma unroll
        for (int s2 = 0; s2 < 16; s2++) p += s_prt[s2 * 32 + t];
        s_ms[t] = p;
    }
    __syncthreads();

    // ---- phase 3: hpart[c] = sum_r relu(P + bias_eff) ----
    {
        float be0 = b1v.x, be1 = b1v.y;
#pragma unroll
        for (int j = 0; j < CD; j++) {
            float mj = s_ms[j] * (1.0f / NA);
            float2 wv = *(const float2*)&s_s[j * HD + c0];   // W1 comm rows
            be0 += mj * wv.x;
            be1 += mj * wv.y;
        }
        float hp0 = 0.f, hp1 = 0.f;
#pragma unroll
        for (int rp = 0; rp < 4; rp++) {
            float x0, x1, y0, y1;
            unpack2(acc[rp][0], x0, x1);
            unpack2(acc[rp][1], y0, y1);
            hp0 += fmaxf(x0 + be0, 0.f) + fmaxf(x1 + be0, 0.f);
            hp1 += fmaxf(y0 + be1, 0.f) + fmaxf(y1 + be1, 0.f);
        }
        *(float2*)&s_prt[rg * HD + c0] = make_float2(hp0, hp1);
    }
    __syncthreads();
    if (t < HD) {
        float v = 0.f;
#pragma unroll
        for (int p = 0; p < 8; p++) v += s_prt[p * HD + t];
        g_hpart[bid * HD + t] = v;          // plain coalesced STG
    }

    bar_arrive(&g_barB);

    // ---- prefetch (hidden behind barB wait): W2 columns only ----
    int cc = t & 127, grp = t >> 7;   // 0..3, 32 k each
    float w2r[32];
#pragma unroll
    for (int i = 0; i < 32; i++) w2r[i] = W2[(grp * 32 + i) * HD + cc];

    bar_wait(&g_barB);

    // ---- parallel hsum reduction -> mean ----
    {
        float v = 0.f;
#pragma unroll 8
        for (int i = 0; i < 32; i++) v += g_hpart[(grp * 32 + i) * HD + cc];
        s_prt[grp * HD + cc] = v;
    }
    __syncthreads();
    if (t < HD) {
        float v = 0.f;
#pragma unroll
        for (int p = 0; p < 4; p++) v += s_prt[p * HD + t];
        s_mh[t] = v * (1.0f / NA);
    }
    __syncthreads();

    // ---- phase 4: g = relu((mean_h @ W2 + b2) @ Wg + bg) ----
    {
        float a = 0.f;
#pragma unroll
        for (int i = 0; i < 32; i++) a += s_mh[grp * 32 + i] * w2r[i];
        s_prt[grp * HD + cc] = a;
        __syncthreads();
        if (t < HD) {
            float v = b2[t];
#pragma unroll
            for (int p = 0; p < 4; p++) v += s_prt[p * HD + t];
            s_h2[t] = v;
        }
        __syncthreads();
        float g2 = 0.f;
#pragma unroll
        for (int seg = 0; seg < 2; seg++) {
            float wgr[16];
#pragma unroll
            for (int i = 0; i < 16; i++)
                wgr[i] = Wg[(grp * 32 + seg * 16 + i) * HD + cc];
#pragma unroll
            for (int i = 0; i < 16; i++)
                g2 += s_h2[grp * 32 + seg * 16 + i] * wgr[i];
        }
        s_prt[grp * HD + cc] = g2;
        __syncthreads();
        if (t < HD) {
            float v = bg[t];
#pragma unroll
            for (int p = 0; p < 4; p++) v += s_prt[p * HD + t];
            s_g[t] = fmaxf(v, 0.f);
        }
        __syncthreads();
    }

    // ---- phase 5: H = l2norm(g + 0.01*noise); heads. 4 rows per warp ----
    {
        float gp0 = s_g[lane +  0], gp1 = s_g[lane + 32];
        float gp2 = s_g[lane + 64], gp3 = s_g[lane + 96];
        float bpv = (lane < 8) ? bp[lane] : 0.f;
        float bvv = bv[0];
        float br0 = br[0], br1 = br[1], br2 = br[2];

#pragma unroll
        for (int i = 0; i < 4; i++) {
            int row = rowb + i;
            float v0 = gp0 + 0.01f * nz[i][0];
            float v1 = gp1 + 0.01f * nz[i][1];
            float v2 = gp2 + 0.01f * nz[i][2];
            float v3 = gp3 + 0.01f * nz[i][3];
            float ss = v0 * v0 + v1 * v1 + v2 * v2 + v3 * v3;
#pragma unroll
            for (int o = 16; o; o >>= 1) ss += __shfl_xor_sync(0xffffffffu, ss, o);
            float rn = 1.f / fmaxf(sqrtf(ss), 1e-12f);
            float h[4] = {v0 * rn, v1 * rn, v2 * rn, v3 * rn};

            float* oh = outH + (size_t)row * HD;
            oh[lane +  0] = h[0];
            oh[lane + 32] = h[1];
            oh[lane + 64] = h[2];
            oh[lane + 96] = h[3];

            float hd_[12];
#pragma unroll
            for (int j = 0; j < 12; j++) hd_[j] = 0.f;
#pragma unroll
            for (int m = 0; m < 4; m++) {
                int k = lane + 32 * m;
                const float4* wrow = (const float4*)&s_hw[k * 12];
                float4 wa = wrow[0], wb2 = wrow[1], wc2 = wrow[2];
                float hv = h[m];
                hd_[0] += hv * wa.x;  hd_[1] += hv * wa.y;
                hd_[2] += hv * wa.z;  hd_[3] += hv * wa.w;
                hd_[4] += hv * wb2.x; hd_[5] += hv * wb2.y;
                hd_[6] += hv * wb2.z; hd_[7] += hv * wb2.w;
                hd_[8] += hv * wc2.x; hd_[9] += hv * wc2.y;
                hd_[10] += hv * wc2.z; hd_[11] += hv * wc2.w;
            }
#pragma unroll
            for (int j = 0; j < 12; j++) {
#pragma unroll
                for (int o = 16; o; o >>= 1)
                    hd_[j] += __shfl_xor_sync(0xffffffffu, hd_[j], o);
            }

            if (lane < 8) {
                outA[(size_t)row * AD + lane] = tanhf(hd_[lane] + bpv);
            } else if (lane == 8) {
                outV[row] = hd_[8] + bvv;
            } else if (lane == 9) {
                float z0 = hd_[9] + br0, z1 = hd_[10] + br1, z2 = hd_[11] + br2;
                float mx = fmaxf(z0, fmaxf(z1, z2));
                float e0 = expf(z0 - mx), e1 = expf(z1 - mx), e2 = expf(z2 - mx);
                float inv = 1.f / (e0 + e1 + e2);
                outR[(size_t)row * 3 + 0] = e0 * inv;
                outR[(size_t)row * 3 + 1] = e1 * inv;
                outR[(size_t)row * 3 + 2] = e2 * inv;
            }
        }
    }

    // ---- epilogue: last CTA resets barrier counters for next graph replay ----
    __syncthreads();
    if (t == 0) {
        __threadfence();
        unsigned v = atomicAdd(&g_done, 1u);
        if (v == (unsigned)(NB - 1)) {
            g_barW = 0u; g_barA = 0u; g_barB = 0u;
            __threadfence();
            g_done = 0u;
        }
    }
}

#define FUSED_SMEM ((4096 + 8192 + 4096 + 32 + 32 + 128 + 128 + 128 + \
                     1024 + 1536) * 4)

extern "C" void kernel_launch(void* const* d_in, const int* in_sizes, int n_in,
                              void* d_out, int out_size) {
    const float* states = (const float*)d_in[0];
    const float* noise  = (const float*)d_in[1];
    const float* W1 = (const float*)d_in[2];
    const float* b1 = (const float*)d_in[3];
    const float* W2 = (const float*)d_in[4];
    const float* b2 = (const float*)d_in[5];
    const float* Wc = (const float*)d_in[6];
    const float* bc = (const float*)d_in[7];
    const float* Wg = (const float*)d_in[8];
    const float* bg = (const float*)d_in[9];
    const float* Wp = (const float*)d_in[10];
    const float* bp = (const float*)d_in[11];
    const float* Wv = (const float*)d_in[12];
    const float* bv = (const float*)d_in[13];
    const float* Wr = (const float*)d_in[14];
    const float* br = (const float*)d_in[15];

    float* outH = (float*)d_out;                       // [N, HD]
    float* outA = outH + (size_t)NA * HD;              // [N, AD]
    float* outV = outA + (size_t)NA * AD;              // [N, 1]
    float* outR = outV + (size_t)NA;                   // [N, 3]

    cudaFuncSetAttribute(kfused, cudaFuncAttributeMaxDynamicSharedMemorySize,
                         FUSED_SMEM);

    kfused<<<NB, NT, FUSED_SMEM>>>(states, noise, W1, b1, W2, b2, Wc, bc,
                                   Wg, bg, Wp, bp, Wv, bv, Wr, br,
                                   outH, outA, outV, outR);
}